// round 4
// baseline (speedup 1.0000x reference)
#include <cuda_runtime.h>
#include <math.h>

namespace {
constexpr int NDIM   = 4;
constexpr int KW     = 32;      // N_WIDTH
constexpr int NN     = 193;     // N_NODES
constexpr int NELEM  = 64;
constexpr int TILE_I = 224;
constexpr int THREADS = 1024;
constexpr int IPW    = TILE_I / 32;           // samples per warp = 7

// float4-granular shared layout
constexpr int OFF_WINV  = 0;                       // float4[(e*4+j)*32+k]  8192
constexpr int OFF_WOUTV = OFF_WINV  + NELEM*4*KW;  // float4[e*32+k]        2048
constexpr int OFF_PHI   = OFF_WOUTV + NELEM*KW;    // float4[TILE_I*4]       896
constexpr int OFF_DPHI  = OFF_PHI   + TILE_I*4;
constexpr int OFF_DDPHI = OFF_DPHI  + TILE_I*4;
constexpr int OFF_ELEM  = OFF_DDPHI + TILE_I*4;    // int4[TILE_I]           224
constexpr int SMEM_V4   = OFF_ELEM  + TILE_I;      // 13152 float4
constexpr int SMEM_BYTES = SMEM_V4 * 16;           // 210432 B
}

__global__ __launch_bounds__(THREADS, 1)
void kann_kernel(const float* __restrict__ x,
                 const float* __restrict__ Win,
                 const float* __restrict__ Wout,
                 float* __restrict__ out,
                 int I)
{
    extern __shared__ float4 smv[];
    float4* sWinV  = smv + OFF_WINV;
    float4* sWoutV = smv + OFF_WOUTV;
    float4* sPhi   = smv + OFF_PHI;
    float4* sDphi  = smv + OFF_DPHI;
    float4* sDdphi = smv + OFF_DDPHI;
    int*    sElem  = (int*)(smv + OFF_ELEM);       // [TILE_I*4]
    const int4* sElem4 = (const int4*)sElem;       // [TILE_I]

    const int tid    = threadIdx.x;
    const int i_base = blockIdx.x * TILE_I;

    // ---- stage W_in taps: sWinV[(e*4+j)*32+k] = {W[k,3e+0,j]..W[k,3e+3,j]} ----
    // lane-consecutive k -> STS.128 addresses stride 16B -> conflict-free.
    for (int idx = tid; idx < NELEM * 4 * KW; idx += THREADS) {
        int e = idx >> 7;
        int j = (idx >> 5) & 3;
        int k = idx & 31;
        const float* g = Win + k * (NN * NDIM) + (3 * e) * NDIM + j;
        sWinV[idx] = make_float4(g[0], g[NDIM], g[2 * NDIM], g[3 * NDIM]);
    }
    // ---- stage W_out taps: sWoutV[e*32+k] = {Wout[k,3e..3e+3]} ----
    for (int idx = tid; idx < NELEM * KW; idx += THREADS) {
        int e = idx >> 5;
        int k = idx & 31;
        const float* g = Wout + k * NN + 3 * e;
        sWoutV[idx] = make_float4(g[0], g[1], g[2], g[3]);
    }

    const float c0 = -0.5625f, c1 = 1.6875f, c2 = -1.6875f, c3 = 0.5625f;
    const float TH = 1.0f / 3.0f;

    // ---- phase 1: per-(sample,dim) basis values + derivatives ----
    if (tid < TILE_I * NDIM) {
        const int li = tid >> 2;
        const int j  = tid & 3;
        const int i  = i_base + li;
        float4 ph = {0,0,0,0}, dp = {0,0,0,0}, dd = {0,0,0,0};
        int ei = 0;
        if (i < I) {
            float xv = x[i * NDIM + j];
            float xs = 192.0f * (xv + 1.0f) / 2.0f;
            float fe = floorf(xs / 3.0f);
            fe = fminf(fmaxf(fe, 0.0f), 63.0f);
            float nl = 3.0f * fe;
            float xr = 2.0f * (xs - nl) / 3.0f - 1.0f;

            float d0 = xr + 1.0f, d1 = xr + TH, d2 = xr - TH, d3 = xr - 1.0f;
            float d01 = d0 * d1, d23 = d2 * d3;
            float d02 = d0 * d2, d03 = d0 * d3, d12 = d1 * d2, d13 = d1 * d3;

            ph.x = c0 * (d1 * d23);
            ph.y = c1 * (d0 * d23);
            ph.z = c2 * (d01 * d3);
            ph.w = c3 * (d01 * d2);
            dp.x = c0 * (d23 + d13 + d12);
            dp.y = c1 * (d23 + d03 + d02);
            dp.z = c2 * (d13 + d03 + d01);
            dp.w = c3 * (d12 + d02 + d01);
            float s = d0 + d1 + d2 + d3;
            dd.x = 2.0f * c0 * (s - d0);
            dd.y = 2.0f * c1 * (s - d1);
            dd.z = 2.0f * c2 * (s - d2);
            dd.w = 2.0f * c3 * (s - d3);
            ei = (int)fe;
        }
        sPhi[tid]   = ph;
        sDphi[tid]  = dp;
        sDdphi[tid] = dd;
        sElem[tid]  = ei;
    }
    __syncthreads();

    // ---- phase 2: warp = one sample, lane = width k ----
    const int warp = tid >> 5;
    const int lane = tid & 31;
    const int IK   = I * KW;

    #pragma unroll
    for (int s = 0; s < IPW; s++) {
        const int li = warp * IPW + s;
        const int i  = i_base + li;
        const int4 e4 = sElem4[li];

        float tv = 0.f, dtv = 0.f, ddtv = 0.f;
        #pragma unroll
        for (int j = 0; j < 4; j++) {
            int e = (j == 0) ? e4.x : (j == 1) ? e4.y : (j == 2) ? e4.z : e4.w;
            int idx = li * 4 + j;
            float4 ph = sPhi[idx];
            float4 dp = sDphi[idx];
            float4 dd = sDdphi[idx];
            float4 w  = sWinV[(e * 4 + j) * KW + lane];
            tv   += w.x * ph.x + w.y * ph.y + w.z * ph.z + w.w * ph.w;
            dtv  += w.x * dp.x + w.y * dp.y + w.z * dp.z + w.w * dp.w;
            ddtv += w.x * dd.x + w.y * dd.y + w.z * dd.z + w.w * dd.w;
        }
        dtv  *= 64.0f;    // 1/delta,   delta = 1/64 exactly
        ddtv *= 4096.0f;  // 1/delta^2

        // outer layer on t, domain [-3,3]
        float xs = 192.0f * (tv + 3.0f) / 6.0f;
        float fe = floorf(xs / 3.0f);
        fe = fminf(fmaxf(fe, 0.0f), 63.0f);
        float nl = 3.0f * fe;
        float xr = 2.0f * (xs - nl) / 3.0f - 1.0f;

        float e0 = xr + 1.0f, e1 = xr + TH, e2 = xr - TH, e3 = xr - 1.0f;
        float e01 = e0 * e1, e23 = e2 * e3;
        float p0 = c0 * (e1 * e23);
        float p1 = c1 * (e0 * e23);
        float p2 = c2 * (e01 * e3);
        float p3 = c3 * (e01 * e2);

        float4 wo = sWoutV[(int)fe * KW + lane];
        float y = p0 * wo.x + p1 * wo.y + p2 * wo.z + p3 * wo.w;

        if (i < I) {
            int o = i * KW + lane;
            out[o]          = y;
            out[o + IK]     = tv;
            out[o + 2 * IK] = dtv;
            out[o + 3 * IK] = ddtv;
        }
    }
}

extern "C" void kernel_launch(void* const* d_in, const int* in_sizes, int n_in,
                              void* d_out, int out_size)
{
    const float* x    = (const float*)d_in[0];
    const float* Win  = (const float*)d_in[1];
    const float* Wout = (const float*)d_in[2];
    float* out = (float*)d_out;

    int I = in_sizes[0] / NDIM;                 // 32768
    int grid = (I + TILE_I - 1) / TILE_I;       // 147

    cudaFuncSetAttribute(kann_kernel,
                         cudaFuncAttributeMaxDynamicSharedMemorySize, SMEM_BYTES);
    kann_kernel<<<grid, THREADS, SMEM_BYTES>>>(x, Win, Wout, out, I);
}

// round 5
// speedup vs baseline: 1.2318x; 1.2318x over previous
#include <cuda_runtime.h>
#include <math.h>

namespace {
constexpr int NDIM   = 4;
constexpr int KW     = 32;      // N_WIDTH total
constexpr int KH     = 16;      // widths per CTA (k-split across 2 CTAs)
constexpr int KS     = 17;      // padded k-stride (odd => conflict-free staging)
constexpr int NN     = 193;     // N_NODES
constexpr int TILE_I = 224;
constexpr int THREADS = 1024;
constexpr int IPW    = TILE_I / 32;           // samples per warp = 7

constexpr int WIN_ROWS  = NN * NDIM;          // 772 (node*4 + j)
constexpr int WIN_SMEM  = WIN_ROWS * KS;      // 13124 floats
constexpr int WOUT_SMEM = NN * KS;            // 3281 floats

// shared layout (float words)
constexpr int OFF_WIN   = 0;
constexpr int OFF_WOUT  = OFF_WIN + WIN_SMEM;
constexpr int OFF_PHI_RAW = OFF_WOUT + WOUT_SMEM;          // 16405
constexpr int OFF_PHI   = (OFF_PHI_RAW + 3) & ~3;          // 16408, 16B aligned
constexpr int OFF_DPHI  = OFF_PHI  + TILE_I * 4 * 4;
constexpr int OFF_DDPHI = OFF_DPHI + TILE_I * 4 * 4;
constexpr int OFF_NODE  = OFF_DDPHI + TILE_I * 4 * 4;      // int [TILE_I*4]
constexpr int SMEM_FLOATS = OFF_NODE + TILE_I * 4;         // 28056
constexpr int SMEM_BYTES  = SMEM_FLOATS * 4;               // 112224 B -> 2 CTAs/SM

static_assert((OFF_PHI % 4) == 0, "float4 alignment");
static_assert(SMEM_BYTES <= 113 * 1024, "must fit 2 CTAs per SM");
}

__global__ __launch_bounds__(THREADS, 2)
void kann_kernel(const float* __restrict__ x,
                 const float* __restrict__ Win,
                 const float* __restrict__ Wout,
                 float* __restrict__ out,
                 int I)
{
    extern __shared__ float sm[];
    float*  sWin   = sm + OFF_WIN;
    float*  sWout  = sm + OFF_WOUT;
    float4* sPhi   = (float4*)(sm + OFF_PHI);
    float4* sDphi  = (float4*)(sm + OFF_DPHI);
    float4* sDdphi = (float4*)(sm + OFF_DDPHI);
    int*    sNode  = (int*)(sm + OFF_NODE);

    const int tid    = threadIdx.x;
    const int i_base = blockIdx.x * TILE_I;
    const int k0     = blockIdx.y * KH;        // this CTA's width offset

    // ---- stage this CTA's half of W_in / W_out ----
    // consecutive threads -> consecutive r -> global coalesced, smem stride 17
    // (odd) -> banks cycle -> conflict-free STS.
    for (int e = tid; e < KH * WIN_ROWS; e += THREADS) {
        int kk = e / WIN_ROWS;
        int r  = e - kk * WIN_ROWS;            // node*4 + j
        sWin[r * KS + kk] = Win[(k0 + kk) * WIN_ROWS + r];
    }
    for (int e = tid; e < KH * NN; e += THREADS) {
        int kk   = e / NN;
        int node = e - kk * NN;
        sWout[node * KS + kk] = Wout[(k0 + kk) * NN + node];
    }

    const float c0 = -0.5625f, c1 = 1.6875f, c2 = -1.6875f, c3 = 0.5625f;
    const float TH = 1.0f / 3.0f;

    // ---- phase 1: per-(sample,dim) basis values + derivatives ----
    if (tid < TILE_I * NDIM) {
        const int li = tid >> 2;
        const int j  = tid & 3;
        const int i  = i_base + li;
        if (i < I) {
            float xv = x[i * NDIM + j];
            float xs = 192.0f * (xv + 1.0f) / 2.0f;
            float fe = floorf(xs / 3.0f);
            fe = fminf(fmaxf(fe, 0.0f), 63.0f);
            float nl = 3.0f * fe;
            float xr = 2.0f * (xs - nl) / 3.0f - 1.0f;

            float d0 = xr + 1.0f, d1 = xr + TH, d2 = xr - TH, d3 = xr - 1.0f;
            float d01 = d0 * d1, d23 = d2 * d3;
            float d02 = d0 * d2, d03 = d0 * d3, d12 = d1 * d2, d13 = d1 * d3;

            float4 ph, dp, dd;
            ph.x = c0 * (d1 * d23);
            ph.y = c1 * (d0 * d23);
            ph.z = c2 * (d01 * d3);
            ph.w = c3 * (d01 * d2);
            dp.x = c0 * (d23 + d13 + d12);
            dp.y = c1 * (d23 + d03 + d02);
            dp.z = c2 * (d13 + d03 + d01);
            dp.w = c3 * (d12 + d02 + d01);
            float s = d0 + d1 + d2 + d3;
            dd.x = 2.0f * c0 * (s - d0);
            dd.y = 2.0f * c1 * (s - d1);
            dd.z = 2.0f * c2 * (s - d2);
            dd.w = 2.0f * c3 * (s - d3);

            sPhi[tid]   = ph;
            sDphi[tid]  = dp;
            sDdphi[tid] = dd;
            sNode[tid]  = 3 * (int)fe;
        } else {
            sPhi[tid]   = make_float4(0.f, 0.f, 0.f, 0.f);
            sDphi[tid]  = make_float4(0.f, 0.f, 0.f, 0.f);
            sDdphi[tid] = make_float4(0.f, 0.f, 0.f, 0.f);
            sNode[tid]  = 0;
        }
    }
    __syncthreads();

    // ---- phase 2: warp = 2 samples (half-warp each), lane%16 = width kk ----
    const int warp = tid >> 5;
    const int lane = tid & 31;
    const int sw   = lane >> 4;                // which sample of the pair
    const int kk   = lane & 15;
    const int IK   = I * KW;

    #pragma unroll
    for (int it = 0; it < 4; it++) {
        const int sraw = 2 * it + sw;          // 0..7
        const int s    = sraw < IPW ? sraw : IPW - 1;   // clamp, masked store
        const int li   = warp * IPW + s;
        const int i    = i_base + li;
        const bool valid = (sraw < IPW) && (i < I);

        float tv = 0.f, dtv = 0.f, ddtv = 0.f;
        #pragma unroll
        for (int j = 0; j < 4; j++) {
            int idx  = li * 4 + j;
            int node = sNode[idx];
            float4 ph = sPhi[idx];
            float4 dp = sDphi[idx];
            float4 dd = sDdphi[idx];
            const float* wb = sWin + (node * 4 + j) * KS + kk;
            float w0 = wb[0 * 4 * KS];
            float w1 = wb[1 * 4 * KS];
            float w2 = wb[2 * 4 * KS];
            float w3 = wb[3 * 4 * KS];
            tv   += w0 * ph.x + w1 * ph.y + w2 * ph.z + w3 * ph.w;
            dtv  += w0 * dp.x + w1 * dp.y + w2 * dp.z + w3 * dp.w;
            ddtv += w0 * dd.x + w1 * dd.y + w2 * dd.z + w3 * dd.w;
        }
        dtv  *= 64.0f;    // 1/delta,   delta = 1/64 exactly
        ddtv *= 4096.0f;  // 1/delta^2

        // outer layer on t, domain [-3,3]
        float xs = 192.0f * (tv + 3.0f) / 6.0f;
        float fe = floorf(xs / 3.0f);
        fe = fminf(fmaxf(fe, 0.0f), 63.0f);
        float nl = 3.0f * fe;
        float xr = 2.0f * (xs - nl) / 3.0f - 1.0f;

        float e0 = xr + 1.0f, e1 = xr + TH, e2 = xr - TH, e3 = xr - 1.0f;
        float e01 = e0 * e1, e23 = e2 * e3;
        float p0 = c0 * (e1 * e23);
        float p1 = c1 * (e0 * e23);
        float p2 = c2 * (e01 * e3);
        float p3 = c3 * (e01 * e2);

        const float* wo = sWout + (3 * (int)fe) * KS + kk;
        float y = p0 * wo[0] + p1 * wo[KS] + p2 * wo[2 * KS] + p3 * wo[3 * KS];

        if (valid) {
            int o = i * KW + k0 + kk;
            out[o]          = y;
            out[o + IK]     = tv;
            out[o + 2 * IK] = dtv;
            out[o + 3 * IK] = ddtv;
        }
    }
}

extern "C" void kernel_launch(void* const* d_in, const int* in_sizes, int n_in,
                              void* d_out, int out_size)
{
    const float* x    = (const float*)d_in[0];
    const float* Win  = (const float*)d_in[1];
    const float* Wout = (const float*)d_in[2];
    float* out = (float*)d_out;

    int I = in_sizes[0] / NDIM;                 // 32768
    dim3 grid((I + TILE_I - 1) / TILE_I, 2);    // 147 x 2 = 294 CTAs

    cudaFuncSetAttribute(kann_kernel,
                         cudaFuncAttributeMaxDynamicSharedMemorySize, SMEM_BYTES);
    kann_kernel<<<grid, THREADS, SMEM_BYTES>>>(x, Win, Wout, out, I);
}

// round 6
// speedup vs baseline: 1.3607x; 1.1047x over previous
#include <cuda_runtime.h>
#include <math.h>

namespace {
constexpr int NDIM   = 4;
constexpr int KW     = 32;      // N_WIDTH
constexpr int NN     = 193;     // N_NODES
constexpr int NELEM  = 64;
constexpr int TILE_I = 224;
constexpr int THREADS = 1024;
constexpr int IPW    = TILE_I / 32;           // samples per warp = 7

constexpr int NTAP_WIN  = NELEM * 4 * KW;     // 8192 float4  (tap table W_in)
constexpr int NTAP_WOUT = NELEM * KW;         // 2048 float4  (tap table W_out)
constexpr int NTAP      = NTAP_WIN + NTAP_WOUT;

// smem layout in float4 units
constexpr int OFF_WIN4  = 0;                        // [ (e*4+j)*32 + k ]
constexpr int OFF_WOUT4 = OFF_WIN4  + NTAP_WIN;     // [ e*32 + k ]
constexpr int OFF_PHI   = OFF_WOUT4 + NTAP_WOUT;    // [TILE_I*4]
constexpr int OFF_DPHI  = OFF_PHI   + TILE_I * 4;
constexpr int OFF_DDPHI = OFF_DPHI  + TILE_I * 4;
constexpr int OFF_ELEM  = OFF_DDPHI + TILE_I * 4;   // int4 [TILE_I]
constexpr int SMEM_V4   = OFF_ELEM  + TILE_I;       // 13152
constexpr int SMEM_BYTES = SMEM_V4 * 16;            // 210432 B (1 CTA/SM)
}

// scratch tap tables, built by prep kernel each call (deterministic)
__device__ float4 g_tap[NTAP];

__global__ void kann_prep(const float* __restrict__ Win,
                          const float* __restrict__ Wout)
{
    int t = blockIdx.x * blockDim.x + threadIdx.x;
    if (t < NTAP_WIN) {
        int k   = t & 31;
        int e4j = t >> 5;
        int j   = e4j & 3;
        int e   = e4j >> 2;
        const float* g = Win + k * (NN * NDIM) + (3 * e) * NDIM + j;
        g_tap[t] = make_float4(g[0], g[NDIM], g[2 * NDIM], g[3 * NDIM]);
    } else if (t < NTAP) {
        int u = t - NTAP_WIN;
        int k = u & 31;
        int e = u >> 5;
        const float* g = Wout + k * NN + 3 * e;
        g_tap[t] = make_float4(g[0], g[1], g[2], g[3]);
    }
}

__global__ __launch_bounds__(THREADS, 1)
void kann_kernel(const float* __restrict__ x,
                 float* __restrict__ out,
                 int I)
{
    extern __shared__ float4 smv[];
    float4* sWin4  = smv + OFF_WIN4;
    float4* sWout4 = smv + OFF_WOUT4;
    float4* sPhi   = smv + OFF_PHI;
    float4* sDphi  = smv + OFF_DPHI;
    float4* sDdphi = smv + OFF_DDPHI;
    int*    sElem  = (int*)(smv + OFF_ELEM);     // [TILE_I*4]
    const int4* sElem4 = (const int4*)sElem;     // [TILE_I]

    const int tid    = threadIdx.x;
    const int i_base = blockIdx.x * TILE_I;

    // ---- stage tap tables: pure coalesced LDG.128 -> conflict-free STS.128 ----
    #pragma unroll
    for (int it = 0; it < NTAP / THREADS; it++) {
        int idx = it * THREADS + tid;
        smv[idx] = g_tap[idx];
    }

    const float c0 = -0.5625f, c1 = 1.6875f, c2 = -1.6875f, c3 = 0.5625f;
    const float TH = 1.0f / 3.0f;

    // ---- phase 1: per-(sample,dim) basis values + derivatives ----
    if (tid < TILE_I * NDIM) {
        const int li = tid >> 2;
        const int j  = tid & 3;
        const int i  = i_base + li;
        float4 ph = {0,0,0,0}, dp = {0,0,0,0}, dd = {0,0,0,0};
        int ei = 0;
        if (i < I) {
            float xv = x[i * NDIM + j];
            float xs = 192.0f * (xv + 1.0f) / 2.0f;
            float fe = floorf(xs / 3.0f);
            fe = fminf(fmaxf(fe, 0.0f), 63.0f);
            float nl = 3.0f * fe;
            float xr = 2.0f * (xs - nl) / 3.0f - 1.0f;

            float d0 = xr + 1.0f, d1 = xr + TH, d2 = xr - TH, d3 = xr - 1.0f;
            float d01 = d0 * d1, d23 = d2 * d3;
            float d02 = d0 * d2, d03 = d0 * d3, d12 = d1 * d2, d13 = d1 * d3;

            ph.x = c0 * (d1 * d23);
            ph.y = c1 * (d0 * d23);
            ph.z = c2 * (d01 * d3);
            ph.w = c3 * (d01 * d2);
            dp.x = c0 * (d23 + d13 + d12);
            dp.y = c1 * (d23 + d03 + d02);
            dp.z = c2 * (d13 + d03 + d01);
            dp.w = c3 * (d12 + d02 + d01);
            float s = d0 + d1 + d2 + d3;
            dd.x = 2.0f * c0 * (s - d0);
            dd.y = 2.0f * c1 * (s - d1);
            dd.z = 2.0f * c2 * (s - d2);
            dd.w = 2.0f * c3 * (s - d3);
            ei = (int)fe;
        }
        sPhi[tid]   = ph;
        sDphi[tid]  = dp;
        sDdphi[tid] = dd;
        sElem[tid]  = ei;
    }
    __syncthreads();

    // ---- phase 2: warp = one sample, lane = width k ----
    const int warp = tid >> 5;
    const int lane = tid & 31;
    const int IK   = I * KW;

    #pragma unroll
    for (int s = 0; s < IPW; s++) {
        const int li = warp * IPW + s;
        const int i  = i_base + li;
        const int4 e4 = sElem4[li];

        float tv = 0.f, dtv = 0.f, ddtv = 0.f;
        #pragma unroll
        for (int j = 0; j < 4; j++) {
            int e = (j == 0) ? e4.x : (j == 1) ? e4.y : (j == 2) ? e4.z : e4.w;
            int idx = li * 4 + j;
            float4 ph = sPhi[idx];
            float4 dp = sDphi[idx];
            float4 dd = sDdphi[idx];
            float4 w  = sWin4[((e << 2) | j) * KW + lane];   // LDS.128, lane-contiguous
            tv   += w.x * ph.x + w.y * ph.y + w.z * ph.z + w.w * ph.w;
            dtv  += w.x * dp.x + w.y * dp.y + w.z * dp.z + w.w * dp.w;
            ddtv += w.x * dd.x + w.y * dd.y + w.z * dd.z + w.w * dd.w;
        }
        dtv  *= 64.0f;    // 1/delta,   delta = 1/64 exactly
        ddtv *= 4096.0f;  // 1/delta^2

        // outer layer on t, domain [-3,3]
        float xs = 192.0f * (tv + 3.0f) / 6.0f;
        float fe = floorf(xs / 3.0f);
        fe = fminf(fmaxf(fe, 0.0f), 63.0f);
        float nl = 3.0f * fe;
        float xr = 2.0f * (xs - nl) / 3.0f - 1.0f;

        float e0 = xr + 1.0f, e1 = xr + TH, e2 = xr - TH, e3 = xr - 1.0f;
        float e01 = e0 * e1, e23 = e2 * e3;
        float p0 = c0 * (e1 * e23);
        float p1 = c1 * (e0 * e23);
        float p2 = c2 * (e01 * e3);
        float p3 = c3 * (e01 * e2);

        float4 wo = sWout4[(int)fe * KW + lane];             // LDS.128
        float y = p0 * wo.x + p1 * wo.y + p2 * wo.z + p3 * wo.w;

        if (i < I) {
            int o = i * KW + lane;
            out[o]          = y;
            out[o + IK]     = tv;
            out[o + 2 * IK] = dtv;
            out[o + 3 * IK] = ddtv;
        }
    }
}

extern "C" void kernel_launch(void* const* d_in, const int* in_sizes, int n_in,
                              void* d_out, int out_size)
{
    const float* x    = (const float*)d_in[0];
    const float* Win  = (const float*)d_in[1];
    const float* Wout = (const float*)d_in[2];
    float* out = (float*)d_out;

    int I = in_sizes[0] / NDIM;                 // 32768
    int grid = (I + TILE_I - 1) / TILE_I;       // 147

    kann_prep<<<(NTAP + 255) / 256, 256>>>(Win, Wout);

    cudaFuncSetAttribute(kann_kernel,
                         cudaFuncAttributeMaxDynamicSharedMemorySize, SMEM_BYTES);
    kann_kernel<<<grid, THREADS, SMEM_BYTES>>>(x, out, I);
}

// round 7
// speedup vs baseline: 1.5861x; 1.1656x over previous
#include <cuda_runtime.h>
#include <math.h>

namespace {
constexpr int NDIM   = 4;
constexpr int KW     = 32;      // N_WIDTH
constexpr int NN     = 193;     // N_NODES
constexpr int NELEM  = 64;
constexpr int TILE_I = 224;
constexpr int THREADS = 1024;
constexpr int IPW    = TILE_I / 32;            // samples per warp = 7

constexpr int NC_IN  = NELEM * 4 * KW;         // 8192 float4 coeff sets (inner)
constexpr int NC_OUT = NELEM * KW;             // 2048 float4 coeff sets (outer)
constexpr int NC     = NC_IN + NC_OUT;         // 10240

// smem layout in float4 units
constexpr int OFF_CIN  = 0;                    // [(e*4+j)*32 + k] -> a0..a3
constexpr int OFF_COUT = OFF_CIN  + NC_IN;     // [e*32 + k]      -> b0..b3
constexpr int OFF_XR   = OFF_COUT + NC_OUT;    // float4 [TILE_I]  xr per dim
constexpr int OFF_E4   = OFF_XR   + TILE_I;    // int4   [TILE_I]  elem per dim
constexpr int SMEM_V4  = OFF_E4   + TILE_I;    // 10688
constexpr int SMEM_BYTES = SMEM_V4 * 16;       // 171008 B (1 CTA/SM)
}

// coefficient tables, rebuilt by prep kernel each call (deterministic)
__device__ float4 g_coef[NC];

// basis -> monomial matrix for cubic Lagrange on nodes {-1,-1/3,1/3,1}
// gamma[p][m]: phi_p(x) = sum_m gamma[p][m] x^m
__global__ void kann_prep(const float* __restrict__ Win,
                          const float* __restrict__ Wout)
{
    const float g00 = -0.0625f, g01 =  0.0625f, g02 =  0.5625f, g03 = -0.5625f;
    const float g10 =  0.5625f, g11 = -1.6875f, g12 = -0.5625f, g13 =  1.6875f;
    const float g20 =  0.5625f, g21 =  1.6875f, g22 = -0.5625f, g23 = -1.6875f;
    const float g30 = -0.0625f, g31 = -0.0625f, g32 =  0.5625f, g33 =  0.5625f;

    int t = blockIdx.x * blockDim.x + threadIdx.x;
    if (t < NC_IN) {
        int k   = t & 31;
        int e4j = t >> 5;
        int j   = e4j & 3;
        int e   = e4j >> 2;
        const float* g = Win + k * (NN * NDIM) + (3 * e) * NDIM + j;
        float w0 = g[0], w1 = g[NDIM], w2 = g[2 * NDIM], w3 = g[3 * NDIM];
        float4 a;
        a.x = w0 * g00 + w1 * g10 + w2 * g20 + w3 * g30;
        a.y = w0 * g01 + w1 * g11 + w2 * g21 + w3 * g31;
        a.z = w0 * g02 + w1 * g12 + w2 * g22 + w3 * g32;
        a.w = w0 * g03 + w1 * g13 + w2 * g23 + w3 * g33;
        g_coef[t] = a;
    } else if (t < NC) {
        int u = t - NC_IN;
        int k = u & 31;
        int e = u >> 5;
        const float* g = Wout + k * NN + 3 * e;
        float w0 = g[0], w1 = g[1], w2 = g[2], w3 = g[3];
        float4 b;
        b.x = w0 * g00 + w1 * g10 + w2 * g20 + w3 * g30;
        b.y = w0 * g01 + w1 * g11 + w2 * g21 + w3 * g31;
        b.z = w0 * g02 + w1 * g12 + w2 * g22 + w3 * g32;
        b.w = w0 * g03 + w1 * g13 + w2 * g23 + w3 * g33;
        g_coef[t] = b;
    }
}

__global__ __launch_bounds__(THREADS, 1)
void kann_kernel(const float* __restrict__ x,
                 float* __restrict__ out,
                 int I)
{
    extern __shared__ float4 smv[];
    float4* sCin  = smv + OFF_CIN;
    float4* sCout = smv + OFF_COUT;
    float4* sXR   = smv + OFF_XR;
    int4*   sE4   = (int4*)(smv + OFF_E4);

    const int tid    = threadIdx.x;
    const int i_base = blockIdx.x * TILE_I;

    // ---- stage coefficient tables: coalesced LDG.128 -> conflict-free STS.128
    for (int idx = tid; idx < SMEM_V4 - 2 * TILE_I; idx += THREADS)
        smv[idx] = g_coef[idx];

    // ---- phase 1: per-sample transform (xr, element) for all 4 dims ----
    if (tid < TILE_I) {
        const int i = i_base + tid;
        float4 xr4 = {0.f, 0.f, 0.f, 0.f};
        int4   e4  = {0, 0, 0, 0};
        if (i < I) {
            float4 xv = ((const float4*)x)[i];
            #pragma unroll
            for (int j = 0; j < 4; j++) {
                float v  = (j == 0) ? xv.x : (j == 1) ? xv.y : (j == 2) ? xv.z : xv.w;
                float xs = 192.0f * (v + 1.0f) / 2.0f;
                float fe = floorf(xs / 3.0f);
                fe = fminf(fmaxf(fe, 0.0f), 63.0f);
                float nl = 3.0f * fe;
                float xr = 2.0f * (xs - nl) / 3.0f - 1.0f;
                if (j == 0) { xr4.x = xr; e4.x = (int)fe; }
                if (j == 1) { xr4.y = xr; e4.y = (int)fe; }
                if (j == 2) { xr4.z = xr; e4.z = (int)fe; }
                if (j == 3) { xr4.w = xr; e4.w = (int)fe; }
            }
        }
        sXR[tid] = xr4;
        sE4[tid] = e4;
    }
    __syncthreads();

    // ---- phase 2: warp = one sample, lane = width k ----
    const int warp = tid >> 5;
    const int lane = tid & 31;
    const int IK   = I * KW;

    #pragma unroll
    for (int s = 0; s < IPW; s++) {
        const int li = warp * IPW + s;
        const int i  = i_base + li;
        const float4 xr4 = sXR[li];
        const int4   e4  = sE4[li];

        float tv = 0.f, dtv = 0.f, ddtv = 0.f;
        #pragma unroll
        for (int j = 0; j < 4; j++) {
            float xr = (j == 0) ? xr4.x : (j == 1) ? xr4.y : (j == 2) ? xr4.z : xr4.w;
            int   e  = (j == 0) ? e4.x  : (j == 1) ? e4.y  : (j == 2) ? e4.z  : e4.w;
            float4 a = sCin[((e << 2) | j) * KW + lane];   // LDS.128
            // simultaneous Horner: p, p', p''/2 share intermediates
            float h1 = fmaf(a.w, xr, a.z);
            float h2 = fmaf(h1,  xr, a.y);
            float h3 = fmaf(h2,  xr, a.x);
            float q2 = fmaf(a.w, xr, h1);
            float q3 = fmaf(q2,  xr, h2);
            float r  = fmaf(a.w, xr, q2);
            tv   += h3;
            dtv  += q3;
            ddtv += r;
        }
        dtv  *= 64.0f;    // p'/delta,      delta = 1/64 exactly
        ddtv *= 8192.0f;  // 2*r/delta^2

        // outer layer on t, domain [-3,3]
        float xs = 192.0f * (tv + 3.0f) / 6.0f;
        float fe = floorf(xs / 3.0f);
        fe = fminf(fmaxf(fe, 0.0f), 63.0f);
        float nl = 3.0f * fe;
        float xr = 2.0f * (xs - nl) / 3.0f - 1.0f;

        float4 b = sCout[(int)fe * KW + lane];             // LDS.128
        float y = fmaf(fmaf(fmaf(b.w, xr, b.z), xr, b.y), xr, b.x);

        if (i < I) {
            int o = i * KW + lane;
            out[o]          = y;
            out[o + IK]     = tv;
            out[o + 2 * IK] = dtv;
            out[o + 3 * IK] = ddtv;
        }
    }
}

extern "C" void kernel_launch(void* const* d_in, const int* in_sizes, int n_in,
                              void* d_out, int out_size)
{
    const float* x    = (const float*)d_in[0];
    const float* Win  = (const float*)d_in[1];
    const float* Wout = (const float*)d_in[2];
    float* out = (float*)d_out;

    int I = in_sizes[0] / NDIM;                 // 32768
    int grid = (I + TILE_I - 1) / TILE_I;       // 147

    kann_prep<<<(NC + 255) / 256, 256>>>(Win, Wout);

    cudaFuncSetAttribute(kann_kernel,
                         cudaFuncAttributeMaxDynamicSharedMemorySize, SMEM_BYTES);
    kann_kernel<<<grid, THREADS, SMEM_BYTES>>>(x, out, I);
}